// round 14
// baseline (speedup 1.0000x reference)
#include <cuda_runtime.h>
#include <cuda_fp16.h>
#include <cstdint>
#include <math.h>

#define T_TOK 8192
#define DIM   1024
#define MLPD  2048
#define NEXP  8

#define BM 128
#define BN 128
#define BK 32          // k halfs per stage

#define AP 20          // uint32 pitch per A row (16 data words + pad) -> conflict-free frags
#define BP 136         // uint32 pitch per B kp-row (128 data words + pad)

#define A_STG (BM * AP)          // 2560 words
#define B_STG ((BK / 2) * BP)    // 2176 words

#define NTHREADS 512
#define NSTAGE 3

// gemm1 dynamic smem: A x3 stages, B1 x3, B3 x3, sTok
#define SM1_WORDS (NSTAGE * A_STG + 2 * NSTAGE * B_STG + BM)
#define SMEM1_BYTES (SM1_WORDS * 4)                       // 83456
// gemm2 dynamic smem: A x3, B x3
#define SM2_WORDS (NSTAGE * (A_STG + B_STG))
#define SMEM2_BYTES (SM2_WORDS * 4)                       // 56832

// ---------------- scratch (static device globals; no allocation) ------------
__device__ int      g_count[NEXP];
__device__ int      g_tok [NEXP * T_TOK];
__device__ float    g_coef[NEXP * T_TOK];
__device__ __half   g_xh  [(size_t)T_TOK * DIM];                 // x in fp16, row-major
__device__ __half   g_h   [(size_t)NEXP * T_TOK * MLPD];         // SwiGLU out, fp16
__device__ uint32_t g_w1h [(size_t)NEXP * (DIM / 2) * MLPD];     // packed {w[2kp][n], w[2kp+1][n]}
__device__ uint32_t g_w3h [(size_t)NEXP * (DIM / 2) * MLPD];
__device__ uint32_t g_w2h [(size_t)NEXP * (MLPD / 2) * DIM];

// ---------------- helpers ---------------------------------------------------
__device__ __forceinline__ uint32_t smem_u32(const void* p) {
    uint32_t a;
    asm("{ .reg .u64 t; cvta.to.shared.u64 t, %1; cvt.u32.u64 %0, t; }" : "=r"(a) : "l"(p));
    return a;
}

__device__ __forceinline__ void cpa16(uint32_t dst, const void* src) {
    asm volatile("cp.async.cg.shared.global [%0], [%1], 16;" :: "r"(dst), "l"(src) : "memory");
}
#define CP_COMMIT()  asm volatile("cp.async.commit_group;" ::: "memory")
#define CP_WAIT(n)   asm volatile("cp.async.wait_group %0;" :: "n"(n) : "memory")

__device__ __forceinline__ void mma16(float c[4], const uint32_t a[4], const uint32_t b[2]) {
    asm volatile(
        "mma.sync.aligned.m16n8k16.row.col.f32.f16.f16.f32 "
        "{%0,%1,%2,%3}, {%4,%5,%6,%7}, {%8,%9}, {%0,%1,%2,%3};"
        : "+f"(c[0]), "+f"(c[1]), "+f"(c[2]), "+f"(c[3])
        : "r"(a[0]), "r"(a[1]), "r"(a[2]), "r"(a[3]), "r"(b[0]), "r"(b[1]));
}

// ---------------- kernel 0: zero counters -----------------------------------
__global__ void k_zero() {
    if (threadIdx.x < NEXP) g_count[threadIdx.x] = 0;
}

// ---------------- kernel 0b: zero output (atomic accumulation target) -------
__global__ void k_zero_out(float* __restrict__ out) {
    size_t i = ((size_t)blockIdx.x * 256 + threadIdx.x) * 4;
    float4 z = {0.f, 0.f, 0.f, 0.f};
    *(float4*)(out + i) = z;
}

// ---------------- kernel 1: router (one warp per token) + x -> fp16 ---------
__global__ void k_router(const float* __restrict__ x, const float* __restrict__ gw) {
    int gtid = blockIdx.x * blockDim.x + threadIdx.x;
    int wid  = gtid >> 5;
    int lane = gtid & 31;
    if (wid >= T_TOK) return;

    const float* xr = x + (size_t)wid * DIM;
    __half*      xo = g_xh + (size_t)wid * DIM;
    float acc[8] = {0.f, 0.f, 0.f, 0.f, 0.f, 0.f, 0.f, 0.f};
    for (int d = lane; d < DIM; d += 32) {
        float xv = __ldg(xr + d);
        xo[d] = __float2half_rn(xv);             // consecutive lanes -> coalesced
        const float4 g0 = *(const float4*)(gw + d * 8);
        const float4 g1 = *(const float4*)(gw + d * 8 + 4);
        acc[0] += xv * g0.x; acc[1] += xv * g0.y; acc[2] += xv * g0.z; acc[3] += xv * g0.w;
        acc[4] += xv * g1.x; acc[5] += xv * g1.y; acc[6] += xv * g1.z; acc[7] += xv * g1.w;
    }
#pragma unroll
    for (int i = 0; i < 8; i++) {
#pragma unroll
        for (int o = 16; o; o >>= 1) acc[i] += __shfl_xor_sync(0xffffffffu, acc[i], o);
    }
    if (lane == 0) {
        int e0 = 0;
#pragma unroll
        for (int i = 1; i < 8; i++) if (acc[i] > acc[e0]) e0 = i;
        int e1 = -1;
#pragma unroll
        for (int i = 0; i < 8; i++) {
            if (i == e0) continue;
            if (e1 < 0 || acc[i] > acc[e1]) e1 = i;
        }
        float m  = acc[e0];
        float p0 = expf(acc[e0] - m);
        float p1 = expf(acc[e1] - m);
        float s  = p0 + p1;

        int pos0 = atomicAdd(&g_count[e0], 1);
        g_tok [e0 * T_TOK + pos0] = wid;
        g_coef[e0 * T_TOK + pos0] = p0 / s;
        int pos1 = atomicAdd(&g_count[e1], 1);
        g_tok [e1 * T_TOK + pos1] = wid;
        g_coef[e1 * T_TOK + pos1] = p1 / s;
    }
}

// ---------------- kernel 1c: pack weights into k-pair fp16 words ------------
// src [e][R][C] fp32 -> dst [e][R/2][C] words, word = {h(src[2kp][n]), h(src[2kp+1][n])}
// grid (C/1024, R/2, E), 256 threads, 4 cols/thread
__global__ void k_pack(const float* __restrict__ src, uint32_t* __restrict__ dst,
                       int R, int C) {
    int e  = blockIdx.z;
    int kp = blockIdx.y;
    int n  = (blockIdx.x * 256 + threadIdx.x) * 4;
    const float4 a = *(const float4*)(src + ((size_t)e * R + 2 * kp    ) * C + n);
    const float4 b = *(const float4*)(src + ((size_t)e * R + 2 * kp + 1) * C + n);
    __half2 h0 = __floats2half2_rn(a.x, b.x);
    __half2 h1 = __floats2half2_rn(a.y, b.y);
    __half2 h2 = __floats2half2_rn(a.z, b.z);
    __half2 h3 = __floats2half2_rn(a.w, b.w);
    uint4 o = { *(uint32_t*)&h0, *(uint32_t*)&h1, *(uint32_t*)&h2, *(uint32_t*)&h3 };
    *(uint4*)(dst + ((size_t)e * (R / 2) + kp) * C + n) = o;
}

// ---------------- kernel 2: GEMM1 (x·w1, x·w3) + SwiGLU ---------------------
// grid (MLPD/BN, T_TOK/BM, NEXP), 512 threads = 16 warps (4M x 4N), warp tile 32x32
// 3-stage cp.async pipeline; issue strictly AFTER the barrier (buffer being
// overwritten = (s-1)%3, which the barrier proves all warps finished reading).
__global__ __launch_bounds__(NTHREADS, 1)
void k_gemm1() {
    int e   = blockIdx.z;
    int cnt = g_count[e];
    int mt  = blockIdx.y;
    if (mt * BM >= cnt) return;
    int nt  = blockIdx.x;

    extern __shared__ uint32_t sm[];
    uint32_t* Abuf = sm;                                   // 3 stages
    uint32_t* B1b  = sm + NSTAGE * A_STG;
    uint32_t* B3b  = sm + NSTAGE * A_STG + NSTAGE * B_STG;
    int*      sTok = (int*)(sm + NSTAGE * A_STG + 2 * NSTAGE * B_STG);

    int tid    = threadIdx.x;
    int warpId = tid >> 5;
    int lane   = tid & 31;
    int gid    = lane >> 2;
    int tig    = lane & 3;
    int mBase  = (warpId & 3) * 32;
    int nBase  = (warpId >> 2) * 32;

    if (tid < BM) {
        int r = mt * BM + tid;
        sTok[tid] = (r < cnt) ? g_tok[e * T_TOK + r] : g_tok[e * T_TOK];
    }
    __syncthreads();

    uint32_t smB = smem_u32(sm);
    int lr  = tid >> 2, lwg = tid & 3;           // A: row, 16B-group
    int lkp = tid >> 5, lng = tid & 31;          // B: kp row, 16B-group
    const __half*   srcA  = g_xh + (size_t)sTok[lr] * DIM + lwg * 8;
    const uint32_t* srcB1 = g_w1h + ((size_t)e * (DIM / 2) + lkp) * MLPD + nt * BN + lng * 4;
    const uint32_t* srcB3 = g_w3h + ((size_t)e * (DIM / 2) + lkp) * MLPD + nt * BN + lng * 4;
    uint32_t dA  = smB + (lr * AP + lwg * 4) * 4;
    uint32_t dB1 = smB + (NSTAGE * A_STG + lkp * BP + lng * 4) * 4;
    uint32_t dB3 = smB + (NSTAGE * A_STG + NSTAGE * B_STG + lkp * BP + lng * 4) * 4;

    auto issue = [&](int s, int buf) {
        cpa16(dA  + buf * A_STG * 4, srcA  + s * BK);
        cpa16(dB1 + buf * B_STG * 4, srcB1 + (size_t)s * (BK / 2) * MLPD);
        cpa16(dB3 + buf * B_STG * 4, srcB3 + (size_t)s * (BK / 2) * MLPD);
        CP_COMMIT();
    };

    float c1[2][4][4], c3[2][4][4];
#pragma unroll
    for (int a = 0; a < 2; a++)
#pragma unroll
        for (int b = 0; b < 4; b++)
#pragma unroll
            for (int d = 0; d < 4; d++) { c1[a][b][d] = 0.f; c3[a][b][d] = 0.f; }

    const int NS = DIM / BK;   // 32
    issue(0, 0);
    issue(1, 1);

    int buf = 0;
    for (int s = 0; s < NS; s++) {
        if (s == NS - 1) { CP_WAIT(0); } else { CP_WAIT(1); }
        __syncthreads();
        if (s + 2 < NS) {
            int nb = buf + 2; if (nb >= NSTAGE) nb -= NSTAGE;
            issue(s + 2, nb);
        }

        const uint32_t* A  = Abuf + buf * A_STG;
        const uint32_t* B1 = B1b  + buf * B_STG;
        const uint32_t* B3 = B3b  + buf * B_STG;
#pragma unroll
        for (int kk = 0; kk < 2; kk++) {      // two k16 chunks per stage
            int kp8 = kk * 8;
            uint32_t a[2][4];
#pragma unroll
            for (int ms = 0; ms < 2; ms++) {
                int rb = mBase + ms * 16;
                a[ms][0] = A[(rb + gid    ) * AP + kp8 + tig    ];
                a[ms][1] = A[(rb + gid + 8) * AP + kp8 + tig    ];
                a[ms][2] = A[(rb + gid    ) * AP + kp8 + tig + 4];
                a[ms][3] = A[(rb + gid + 8) * AP + kp8 + tig + 4];
            }
#pragma unroll
            for (int ns = 0; ns < 4; ns++) {
                int ncol = nBase + ns * 8 + gid;
                uint32_t b1f[2] = { B1[(kp8 + tig) * BP + ncol], B1[(kp8 + tig + 4) * BP + ncol] };
                uint32_t b3f[2] = { B3[(kp8 + tig) * BP + ncol], B3[(kp8 + tig + 4) * BP + ncol] };
                mma16(c1[0][ns], a[0], b1f);
                mma16(c1[1][ns], a[1], b1f);
                mma16(c3[0][ns], a[0], b3f);
                mma16(c3[1][ns], a[1], b3f);
            }
        }
        if (++buf >= NSTAGE) buf = 0;
    }

    // SwiGLU epilogue -> g_h (fp16)
#pragma unroll
    for (int ms = 0; ms < 2; ms++) {
#pragma unroll
        for (int half = 0; half < 2; half++) {
            int grow = mt * BM + mBase + ms * 16 + gid + half * 8;
            if (grow < cnt) {
                size_t rowoff = ((size_t)e * T_TOK + grow) * MLPD;
#pragma unroll
                for (int ns = 0; ns < 4; ns++) {
                    int col = nt * BN + nBase + ns * 8 + tig * 2;
                    float v1a = c1[ms][ns][half * 2 + 0];
                    float v1b = c1[ms][ns][half * 2 + 1];
                    float v3a = c3[ms][ns][half * 2 + 0];
                    float v3b = c3[ms][ns][half * 2 + 1];
                    float ox = v1a / (1.f + __expf(-v1a)) * v3a;
                    float oy = v1b / (1.f + __expf(-v1b)) * v3b;
                    *(__half2*)(g_h + rowoff + col) = __floats2half2_rn(ox, oy);
                }
            }
        }
    }
}

// ---------------- kernel 3: GEMM2 (h·w2) -> atomic scatter into out ---------
// grid (DIM/BN, T_TOK/BM, NEXP), 512 threads, 2 CTAs/SM, 3-stage pipeline
// Each output element gets exactly 2 expert contributions; with a zeroed
// target, (0+a)+b == (0+b)+a exactly in fp32 -> order-independent result.
__global__ __launch_bounds__(NTHREADS, 2)
void k_gemm2(float* __restrict__ out) {
    int e   = blockIdx.z;
    int cnt = g_count[e];
    int mt  = blockIdx.y;
    if (mt * BM >= cnt) return;
    int nt  = blockIdx.x;

    extern __shared__ uint32_t sm[];
    uint32_t* Abuf = sm;
    uint32_t* Bb   = sm + NSTAGE * A_STG;

    int tid    = threadIdx.x;
    int warpId = tid >> 5;
    int lane   = tid & 31;
    int gid    = lane >> 2;
    int tig    = lane & 3;
    int mBase  = (warpId & 3) * 32;
    int nBase  = (warpId >> 2) * 32;

    uint32_t smB = smem_u32(sm);
    int lr  = tid >> 2, lwg = tid & 3;
    int lkp = tid >> 5, lng = tid & 31;
    // rows >= cnt read stale-but-finite h scratch; results discarded.
    const __half*   srcA = g_h + ((size_t)e * T_TOK + (size_t)mt * BM + lr) * MLPD + lwg * 8;
    const uint32_t* srcB = g_w2h + ((size_t)e * (MLPD / 2) + lkp) * DIM + nt * BN + lng * 4;
    uint32_t dA = smB + (lr * AP + lwg * 4) * 4;
    uint32_t dB = smB + (NSTAGE * A_STG + lkp * BP + lng * 4) * 4;

    auto issue = [&](int s, int buf) {
        cpa16(dA + buf * A_STG * 4, srcA + s * BK);
        cpa16(dB + buf * B_STG * 4, srcB + (size_t)s * (BK / 2) * DIM);
        CP_COMMIT();
    };

    float c[2][4][4];
#pragma unroll
    for (int a = 0; a < 2; a++)
#pragma unroll
        for (int b = 0; b < 4; b++)
#pragma unroll
            for (int d = 0; d < 4; d++) c[a][b][d] = 0.f;

    const int NS = MLPD / BK;  // 64
    issue(0, 0);
    issue(1, 1);

    int buf = 0;
    for (int s = 0; s < NS; s++) {
        if (s == NS - 1) { CP_WAIT(0); } else { CP_WAIT(1); }
        __syncthreads();
        if (s + 2 < NS) {
            int nb = buf + 2; if (nb >= NSTAGE) nb -= NSTAGE;
            issue(s + 2, nb);
        }

        const uint32_t* A = Abuf + buf * A_STG;
        const uint32_t* B = Bb   + buf * B_STG;
#pragma unroll
        for (int kk = 0; kk < 2; kk++) {
            int kp8 = kk * 8;
            uint32_t a[2][4];
#pragma unroll
            for (int ms = 0; ms < 2; ms++) {
                int rb = mBase + ms * 16;
                a[ms][0] = A[(rb + gid    ) * AP + kp8 + tig    ];
                a[ms][1] = A[(rb + gid + 8) * AP + kp8 + tig    ];
                a[ms][2] = A[(rb + gid    ) * AP + kp8 + tig + 4];
                a[ms][3] = A[(rb + gid + 8) * AP + kp8 + tig + 4];
            }
#pragma unroll
            for (int ns = 0; ns < 4; ns++) {
                int ncol = nBase + ns * 8 + gid;
                uint32_t bf[2] = { B[(kp8 + tig) * BP + ncol], B[(kp8 + tig + 4) * BP + ncol] };
                mma16(c[0][ns], a[0], bf);
                mma16(c[1][ns], a[1], bf);
            }
        }
        if (++buf >= NSTAGE) buf = 0;
    }

    // scaled atomic scatter directly into the output
#pragma unroll
    for (int ms = 0; ms < 2; ms++) {
#pragma unroll
        for (int half = 0; half < 2; half++) {
            int grow = mt * BM + mBase + ms * 16 + gid + half * 8;
            if (grow < cnt) {
                int   gi = e * T_TOK + grow;
                int   t  = g_tok[gi];
                float cf = g_coef[gi];
                float* op = out + (size_t)t * DIM + nt * BN + nBase;
#pragma unroll
                for (int ns = 0; ns < 4; ns++) {
                    int col = ns * 8 + tig * 2;
                    atomicAdd(op + col,     cf * c[ms][ns][half * 2 + 0]);
                    atomicAdd(op + col + 1, cf * c[ms][ns][half * 2 + 1]);
                }
            }
        }
    }
}

// ---------------- launch -----------------------------------------------------
extern "C" void kernel_launch(void* const* d_in, const int* in_sizes, int n_in,
                              void* d_out, int out_size) {
    const float* x  = (const float*)d_in[0];
    const float* gw = (const float*)d_in[1];
    const float* w1 = (const float*)d_in[2];
    const float* w2 = (const float*)d_in[3];
    const float* w3 = (const float*)d_in[4];

    cudaFuncSetAttribute(k_gemm1, cudaFuncAttributeMaxDynamicSharedMemorySize, SMEM1_BYTES);
    cudaFuncSetAttribute(k_gemm2, cudaFuncAttributeMaxDynamicSharedMemorySize, SMEM2_BYTES);

    k_zero<<<1, 32>>>();
    k_zero_out<<<(T_TOK * DIM / 4) / 256, 256>>>((float*)d_out);
    k_router<<<T_TOK / 8, 256>>>(x, gw);

    uint32_t* w1h; cudaGetSymbolAddress((void**)&w1h, g_w1h);
    uint32_t* w3h; cudaGetSymbolAddress((void**)&w3h, g_w3h);
    uint32_t* w2h; cudaGetSymbolAddress((void**)&w2h, g_w2h);
    k_pack<<<dim3(MLPD / 1024, DIM / 2, NEXP), 256>>>(w1, w1h, DIM, MLPD);
    k_pack<<<dim3(MLPD / 1024, DIM / 2, NEXP), 256>>>(w3, w3h, DIM, MLPD);
    k_pack<<<dim3(DIM / 1024, MLPD / 2, NEXP), 256>>>(w2, w2h, MLPD, DIM);

    k_gemm1<<<dim3(MLPD / BN, T_TOK / BM, NEXP), NTHREADS, SMEM1_BYTES>>>();
    k_gemm2<<<dim3(DIM / BN, T_TOK / BM, NEXP), NTHREADS, SMEM2_BYTES>>>((float*)d_out);
}

// round 15
// speedup vs baseline: 1.0728x; 1.0728x over previous
#include <cuda_runtime.h>
#include <cuda_fp16.h>
#include <cstdint>
#include <math.h>

#define T_TOK 8192
#define DIM   1024
#define MLPD  2048
#define NEXP  8

#define BM 128
#define BN 128
#define BK 32          // k halfs per stage (= 2 k16 blocks = 8 kq rows)

#define AP 20          // uint32 pitch per A row (16 data words + 4 pad)
#define BQ 264         // uint32 pitch per B kq-row (256 data words + 8 pad)

#define A_STG (BM * AP)          // 2560 words
#define B_STG (8 * BQ)           // 2112 words

#define NTHREADS 512
#define NSTAGE 3

#define SM1_WORDS (NSTAGE * A_STG + 2 * NSTAGE * B_STG + BM)
#define SMEM1_BYTES (SM1_WORDS * 4)                       // 81920
#define SM2_WORDS (NSTAGE * (A_STG + B_STG))
#define SMEM2_BYTES (SM2_WORDS * 4)                       // 56064

// ---------------- scratch (static device globals; no allocation) ------------
__device__ int      g_count[NEXP];
__device__ int      g_tok [NEXP * T_TOK];
__device__ int      g_slot[NEXP * T_TOK];
__device__ float    g_coef[NEXP * T_TOK];
__device__ __half   g_xh  [(size_t)T_TOK * DIM];                 // x in fp16
__device__ __half   g_h   [(size_t)NEXP * T_TOK * MLPD];         // SwiGLU out, fp16
// B fragment-packed weights: [e][kq][n] -> uint2 {b0,b1}
// kq = 4*(k16 block) + tig; b0 = {w[16b+2t][n], w[16b+2t+1][n]}, b1 = {+8, +9}
__device__ uint2    g_w1p [(size_t)NEXP * (DIM / 4) * MLPD];
__device__ uint2    g_w3p [(size_t)NEXP * (DIM / 4) * MLPD];
__device__ uint2    g_w2p [(size_t)NEXP * (MLPD / 4) * DIM];
__device__ float    g_out2[2ull * T_TOK * DIM];                  // per-slot combine buffers

// ---------------- helpers ---------------------------------------------------
__device__ __forceinline__ uint32_t smem_u32(const void* p) {
    uint32_t a;
    asm("{ .reg .u64 t; cvta.to.shared.u64 t, %1; cvt.u32.u64 %0, t; }" : "=r"(a) : "l"(p));
    return a;
}

__device__ __forceinline__ void cpa16(uint32_t dst, const void* src) {
    asm volatile("cp.async.cg.shared.global [%0], [%1], 16;" :: "r"(dst), "l"(src) : "memory");
}
#define CP_COMMIT()  asm volatile("cp.async.commit_group;" ::: "memory")
#define CP_WAIT(n)   asm volatile("cp.async.wait_group %0;" :: "n"(n) : "memory")

__device__ __forceinline__ void ldsm4(uint32_t a[4], uint32_t addr) {
    asm volatile("ldmatrix.sync.aligned.m8n8.x4.shared.b16 {%0,%1,%2,%3}, [%4];"
        : "=r"(a[0]), "=r"(a[1]), "=r"(a[2]), "=r"(a[3]) : "r"(addr));
}

__device__ __forceinline__ void mma16(float c[4], const uint32_t a[4],
                                      uint32_t b0, uint32_t b1) {
    asm volatile(
        "mma.sync.aligned.m16n8k16.row.col.f32.f16.f16.f32 "
        "{%0,%1,%2,%3}, {%4,%5,%6,%7}, {%8,%9}, {%0,%1,%2,%3};"
        : "+f"(c[0]), "+f"(c[1]), "+f"(c[2]), "+f"(c[3])
        : "r"(a[0]), "r"(a[1]), "r"(a[2]), "r"(a[3]), "r"(b0), "r"(b1));
}

// ---------------- kernel 0: zero counters -----------------------------------
__global__ void k_zero() {
    if (threadIdx.x < NEXP) g_count[threadIdx.x] = 0;
}

// ---------------- kernel 1: router (one warp per token) + x -> fp16 ---------
__global__ void k_router(const float* __restrict__ x, const float* __restrict__ gw) {
    int gtid = blockIdx.x * blockDim.x + threadIdx.x;
    int wid  = gtid >> 5;
    int lane = gtid & 31;
    if (wid >= T_TOK) return;

    const float* xr = x + (size_t)wid * DIM;
    __half*      xo = g_xh + (size_t)wid * DIM;
    float acc[8] = {0.f, 0.f, 0.f, 0.f, 0.f, 0.f, 0.f, 0.f};
    for (int d = lane; d < DIM; d += 32) {
        float xv = __ldg(xr + d);
        xo[d] = __float2half_rn(xv);
        const float4 g0 = *(const float4*)(gw + d * 8);
        const float4 g1 = *(const float4*)(gw + d * 8 + 4);
        acc[0] += xv * g0.x; acc[1] += xv * g0.y; acc[2] += xv * g0.z; acc[3] += xv * g0.w;
        acc[4] += xv * g1.x; acc[5] += xv * g1.y; acc[6] += xv * g1.z; acc[7] += xv * g1.w;
    }
#pragma unroll
    for (int i = 0; i < 8; i++) {
#pragma unroll
        for (int o = 16; o; o >>= 1) acc[i] += __shfl_xor_sync(0xffffffffu, acc[i], o);
    }
    if (lane == 0) {
        int e0 = 0;
#pragma unroll
        for (int i = 1; i < 8; i++) if (acc[i] > acc[e0]) e0 = i;
        int e1 = -1;
#pragma unroll
        for (int i = 0; i < 8; i++) {
            if (i == e0) continue;
            if (e1 < 0 || acc[i] > acc[e1]) e1 = i;
        }
        float m  = acc[e0];
        float p0 = expf(acc[e0] - m);
        float p1 = expf(acc[e1] - m);
        float s  = p0 + p1;

        int pos0 = atomicAdd(&g_count[e0], 1);
        g_tok [e0 * T_TOK + pos0] = wid;
        g_slot[e0 * T_TOK + pos0] = 0;
        g_coef[e0 * T_TOK + pos0] = p0 / s;
        int pos1 = atomicAdd(&g_count[e1], 1);
        g_tok [e1 * T_TOK + pos1] = wid;
        g_slot[e1 * T_TOK + pos1] = 1;
        g_coef[e1 * T_TOK + pos1] = p1 / s;
    }
}

// ---------------- kernel 1c: pack weights into B-fragment uint2 pairs -------
// src [e][K][N] fp32 -> dst [e][K/4][N] uint2; grid (N/256, K/4, E)
__global__ void k_pack2(const float* __restrict__ src, uint2* __restrict__ dst,
                        int K, int N) {
    int e  = blockIdx.z;
    int kq = blockIdx.y;                 // 0 .. K/4-1
    int b  = kq >> 2, tig = kq & 3;
    int n  = blockIdx.x * 256 + threadIdx.x;
    int k0 = 16 * b + 2 * tig;
    const float* s = src + (size_t)e * K * N + n;
    float f0 = s[(size_t)(k0    ) * N];
    float f1 = s[(size_t)(k0 + 1) * N];
    float f2 = s[(size_t)(k0 + 8) * N];
    float f3 = s[(size_t)(k0 + 9) * N];
    __half2 lo = __floats2half2_rn(f0, f1);
    __half2 hi = __floats2half2_rn(f2, f3);
    uint2 o = { *(uint32_t*)&lo, *(uint32_t*)&hi };
    dst[((size_t)e * (K / 4) + kq) * N + n] = o;
}

// ---------------- kernel 2: GEMM1 (x·w1, x·w3) + SwiGLU ---------------------
// grid (MLPD/BN, T_TOK/BM, NEXP), 512 threads = 16 warps (4M x 4N), warp tile 32x32
__global__ __launch_bounds__(NTHREADS, 1)
void k_gemm1() {
    int e   = blockIdx.z;
    int cnt = g_count[e];
    int mt  = blockIdx.y;
    if (mt * BM >= cnt) return;
    int nt  = blockIdx.x;

    extern __shared__ uint32_t sm[];
    const int B1OFF = NSTAGE * A_STG;
    const int B3OFF = NSTAGE * A_STG + NSTAGE * B_STG;
    int* sTok = (int*)(sm + NSTAGE * A_STG + 2 * NSTAGE * B_STG);

    int tid    = threadIdx.x;
    int warpId = tid >> 5;
    int lane   = tid & 31;
    int gid    = lane >> 2;
    int tig    = lane & 3;
    int mBase  = (warpId & 3) * 32;
    int nBase  = (warpId >> 2) * 32;

    if (tid < BM) {
        int r = mt * BM + tid;
        sTok[tid] = (r < cnt) ? g_tok[e * T_TOK + r] : g_tok[e * T_TOK];
    }
    __syncthreads();

    uint32_t smB = smem_u32(sm);
    // loaders
    int lr  = tid >> 2, lwg = tid & 3;           // A: row, 16B-group
    int lkq = tid >> 6, lng = tid & 63;          // B: kq row, 16B-group (2 uint2)
    const __half* srcA  = g_xh + (size_t)sTok[lr] * DIM + lwg * 8;
    const uint2*  srcB1 = g_w1p + ((size_t)e * (DIM / 4) + lkq) * MLPD + nt * BN + lng * 2;
    const uint2*  srcB3 = g_w3p + ((size_t)e * (DIM / 4) + lkq) * MLPD + nt * BN + lng * 2;
    uint32_t dA  = smB + (lr * AP + lwg * 4) * 4;
    uint32_t dB1 = smB + (B1OFF + lkq * BQ + lng * 4) * 4;
    uint32_t dB3 = smB + (B3OFF + lkq * BQ + lng * 4) * 4;

    auto issue = [&](int s, int buf) {
        cpa16(dA  + buf * A_STG * 4, srcA  + s * BK);
        cpa16(dB1 + buf * B_STG * 4, srcB1 + (size_t)s * 8 * MLPD);
        cpa16(dB3 + buf * B_STG * 4, srcB3 + (size_t)s * 8 * MLPD);
        CP_COMMIT();
    };

    // A ldmatrix per-lane address (m16k16 canonical: row = lane&15, k8 grp = lane>>4)
    uint32_t aA = smB + ((mBase + (lane & 15)) * AP + (lane >> 4) * 4) * 4;
    // B fragment uint2 index base
    int bIdx = tig * (BQ / 2) + nBase + gid;

    float c1[2][4][4], c3[2][4][4];
#pragma unroll
    for (int a = 0; a < 2; a++)
#pragma unroll
        for (int b = 0; b < 4; b++)
#pragma unroll
            for (int d = 0; d < 4; d++) { c1[a][b][d] = 0.f; c3[a][b][d] = 0.f; }

    const int NS = DIM / BK;   // 32
    issue(0, 0);
    issue(1, 1);

    int buf = 0;
    for (int s = 0; s < NS; s++) {
        if (s == NS - 1) { CP_WAIT(0); } else { CP_WAIT(1); }
        __syncthreads();
        if (s + 2 < NS) {
            int nb = buf + 2; if (nb >= NSTAGE) nb -= NSTAGE;
            issue(s + 2, nb);
        }

        const uint2* B1f = (const uint2*)(sm + B1OFF + buf * B_STG);
        const uint2* B3f = (const uint2*)(sm + B3OFF + buf * B_STG);
        uint32_t aBase = aA + buf * A_STG * 4;
#pragma unroll
        for (int kk = 0; kk < 2; kk++) {
            uint32_t a0[4], a1[4];
            ldsm4(a0, aBase + kk * 32);
            ldsm4(a1, aBase + 16 * AP * 4 + kk * 32);
            int kb = bIdx + kk * 4 * (BQ / 2);
#pragma unroll
            for (int ns = 0; ns < 4; ns++) {
                uint2 b1 = B1f[kb + ns * 8];
                uint2 b3 = B3f[kb + ns * 8];
                mma16(c1[0][ns], a0, b1.x, b1.y);
                mma16(c1[1][ns], a1, b1.x, b1.y);
                mma16(c3[0][ns], a0, b3.x, b3.y);
                mma16(c3[1][ns], a1, b3.x, b3.y);
            }
        }
        if (++buf >= NSTAGE) buf = 0;
    }

    // SwiGLU epilogue -> g_h (fp16)
#pragma unroll
    for (int ms = 0; ms < 2; ms++) {
#pragma unroll
        for (int half = 0; half < 2; half++) {
            int grow = mt * BM + mBase + ms * 16 + gid + half * 8;
            if (grow < cnt) {
                size_t rowoff = ((size_t)e * T_TOK + grow) * MLPD;
#pragma unroll
                for (int ns = 0; ns < 4; ns++) {
                    int col = nt * BN + nBase + ns * 8 + tig * 2;
                    float v1a = c1[ms][ns][half * 2 + 0];
                    float v1b = c1[ms][ns][half * 2 + 1];
                    float v3a = c3[ms][ns][half * 2 + 0];
                    float v3b = c3[ms][ns][half * 2 + 1];
                    float ox = v1a / (1.f + __expf(-v1a)) * v3a;
                    float oy = v1b / (1.f + __expf(-v1b)) * v3b;
                    *(__half2*)(g_h + rowoff + col) = __floats2half2_rn(ox, oy);
                }
            }
        }
    }
}

// ---------------- kernel 3: GEMM2 (h·w2, scaled scatter to slot buffers) ----
// grid (DIM/BN, T_TOK/BM, NEXP), 512 threads, 2 CTAs/SM
__global__ __launch_bounds__(NTHREADS, 2)
void k_gemm2() {
    int e   = blockIdx.z;
    int cnt = g_count[e];
    int mt  = blockIdx.y;
    if (mt * BM >= cnt) return;
    int nt  = blockIdx.x;

    extern __shared__ uint32_t sm[];
    const int BOFF = NSTAGE * A_STG;

    int tid    = threadIdx.x;
    int warpId = tid >> 5;
    int lane   = tid & 31;
    int gid    = lane >> 2;
    int tig    = lane & 3;
    int mBase  = (warpId & 3) * 32;
    int nBase  = (warpId >> 2) * 32;

    uint32_t smB = smem_u32(sm);
    int lr  = tid >> 2, lwg = tid & 3;
    int lkq = tid >> 6, lng = tid & 63;
    // rows >= cnt read stale-but-finite h scratch; results discarded.
    const __half* srcA = g_h + ((size_t)e * T_TOK + (size_t)mt * BM + lr) * MLPD + lwg * 8;
    const uint2*  srcB = g_w2p + ((size_t)e * (MLPD / 4) + lkq) * DIM + nt * BN + lng * 2;
    uint32_t dA = smB + (lr * AP + lwg * 4) * 4;
    uint32_t dB = smB + (BOFF + lkq * BQ + lng * 4) * 4;

    auto issue = [&](int s, int buf) {
        cpa16(dA + buf * A_STG * 4, srcA + s * BK);
        cpa16(dB + buf * B_STG * 4, srcB + (size_t)s * 8 * DIM);
        CP_COMMIT();
    };

    uint32_t aA = smB + ((mBase + (lane & 15)) * AP + (lane >> 4) * 4) * 4;
    int bIdx = tig * (BQ / 2) + nBase + gid;

    float c[2][4][4];
#pragma unroll
    for (int a = 0; a < 2; a++)
#pragma unroll
        for (int b = 0; b < 4; b++)
#pragma unroll
            for (int d = 0; d < 4; d++) c[a][b][d] = 0.f;

    const int NS = MLPD / BK;  // 64
    issue(0, 0);
    issue(1, 1);

    int buf = 0;
    for (int s = 0; s < NS; s++) {
        if (s == NS - 1) { CP_WAIT(0); } else { CP_WAIT(1); }
        __syncthreads();
        if (s + 2 < NS) {
            int nb = buf + 2; if (nb >= NSTAGE) nb -= NSTAGE;
            issue(s + 2, nb);
        }

        const uint2* Bf = (const uint2*)(sm + BOFF + buf * B_STG);
        uint32_t aBase = aA + buf * A_STG * 4;
#pragma unroll
        for (int kk = 0; kk < 2; kk++) {
            uint32_t a0[4], a1[4];
            ldsm4(a0, aBase + kk * 32);
            ldsm4(a1, aBase + 16 * AP * 4 + kk * 32);
            int kb = bIdx + kk * 4 * (BQ / 2);
#pragma unroll
            for (int ns = 0; ns < 4; ns++) {
                uint2 b = Bf[kb + ns * 8];
                mma16(c[0][ns], a0, b.x, b.y);
                mma16(c[1][ns], a1, b.x, b.y);
            }
        }
        if (++buf >= NSTAGE) buf = 0;
    }

    // scaled scatter into per-slot buffers (each (slot, token) cell written once)
#pragma unroll
    for (int ms = 0; ms < 2; ms++) {
#pragma unroll
        for (int half = 0; half < 2; half++) {
            int grow = mt * BM + mBase + ms * 16 + gid + half * 8;
            if (grow < cnt) {
                int   gi = e * T_TOK + grow;
                int   t  = g_tok[gi];
                int   sl = g_slot[gi];
                float cf = g_coef[gi];
                float* op = g_out2 + ((size_t)sl * T_TOK + t) * DIM + nt * BN + nBase;
#pragma unroll
                for (int ns = 0; ns < 4; ns++) {
                    int col = ns * 8 + tig * 2;
                    float2 o;
                    o.x = cf * c[ms][ns][half * 2 + 0];
                    o.y = cf * c[ms][ns][half * 2 + 1];
                    *(float2*)(op + col) = o;
                }
            }
        }
    }
}

// ---------------- kernel 4: combine slots -> output -------------------------
__global__ void k_combine(float* __restrict__ out) {
    size_t i = ((size_t)blockIdx.x * 256 + threadIdx.x) * 4;
    float4 a = *(const float4*)(g_out2 + i);
    float4 b = *(const float4*)(g_out2 + (size_t)T_TOK * DIM + i);
    float4 r;
    r.x = a.x + b.x; r.y = a.y + b.y; r.z = a.z + b.z; r.w = a.w + b.w;
    *(float4*)(out + i) = r;
}

// ---------------- launch -----------------------------------------------------
extern "C" void kernel_launch(void* const* d_in, const int* in_sizes, int n_in,
                              void* d_out, int out_size) {
    const float* x  = (const float*)d_in[0];
    const float* gw = (const float*)d_in[1];
    const float* w1 = (const float*)d_in[2];
    const float* w2 = (const float*)d_in[3];
    const float* w3 = (const float*)d_in[4];

    cudaFuncSetAttribute(k_gemm1, cudaFuncAttributeMaxDynamicSharedMemorySize, SMEM1_BYTES);
    cudaFuncSetAttribute(k_gemm2, cudaFuncAttributeMaxDynamicSharedMemorySize, SMEM2_BYTES);

    k_zero<<<1, 32>>>();
    k_router<<<T_TOK / 8, 256>>>(x, gw);

    uint2* w1p; cudaGetSymbolAddress((void**)&w1p, g_w1p);
    uint2* w3p; cudaGetSymbolAddress((void**)&w3p, g_w3p);
    uint2* w2p; cudaGetSymbolAddress((void**)&w2p, g_w2p);
    k_pack2<<<dim3(MLPD / 256, DIM / 4, NEXP), 256>>>(w1, w1p, DIM, MLPD);
    k_pack2<<<dim3(MLPD / 256, DIM / 4, NEXP), 256>>>(w3, w3p, DIM, MLPD);
    k_pack2<<<dim3(DIM / 256, MLPD / 4, NEXP), 256>>>(w2, w2p, MLPD, DIM);

    k_gemm1<<<dim3(MLPD / BN, T_TOK / BM, NEXP), NTHREADS, SMEM1_BYTES>>>();
    k_gemm2<<<dim3(DIM / BN, T_TOK / BM, NEXP), NTHREADS, SMEM2_BYTES>>>();

    k_combine<<<(T_TOK * DIM / 4) / 256, 256>>>((float*)d_out);
}

// round 16
// speedup vs baseline: 1.1774x; 1.0974x over previous
#include <cuda_runtime.h>
#include <cuda_fp16.h>
#include <cstdint>
#include <math.h>

#define T_TOK 8192
#define DIM   1024
#define MLPD  2048
#define NEXP  8

#define BM 128
#define BN 128
#define BK 64          // k halfs per stage (= 4 k16 blocks = 16 kq rows)

#define AP 36          // uint32 pitch per A row (32 data words + 4 pad)
#define BQ 264         // uint32 pitch per B kq-row (256 data words + 8 pad)

#define A_STG (BM * AP)          // 4608 words
#define B_STG (16 * BQ)          // 4224 words

#define NTHREADS 512
#define NST1 3                   // gemm1 stages
#define NST2 2                   // gemm2 stages

#define SM1_WORDS (NST1 * (A_STG + 2 * B_STG) + BM)
#define SMEM1_BYTES (SM1_WORDS * 4)                 // 157184
#define SM2_WORDS (NST2 * (A_STG + B_STG))
#define SMEM2_BYTES (SM2_WORDS * 4)                 // 70656

// ---------------- scratch (static device globals; no allocation) ------------
__device__ int      g_count[NEXP];
__device__ int      g_tok [NEXP * T_TOK];
__device__ int      g_slot[NEXP * T_TOK];
__device__ float    g_coef[NEXP * T_TOK];
__device__ __half   g_xh  [(size_t)T_TOK * DIM];                 // x in fp16
__device__ __half   g_h   [(size_t)NEXP * T_TOK * MLPD];         // SwiGLU out, fp16
// B fragment-packed weights: [e][kq][n] -> uint2 {b0,b1}
// kq = 4*(k16 block) + tig; b0 = {w[16b+2t][n], w[16b+2t+1][n]}, b1 = {+8, +9}
__device__ uint2    g_w1p [(size_t)NEXP * (DIM / 4) * MLPD];
__device__ uint2    g_w3p [(size_t)NEXP * (DIM / 4) * MLPD];
__device__ uint2    g_w2p [(size_t)NEXP * (MLPD / 4) * DIM];
__device__ float    g_out2[2ull * T_TOK * DIM];                  // per-slot combine buffers

// ---------------- helpers ---------------------------------------------------
__device__ __forceinline__ uint32_t smem_u32(const void* p) {
    uint32_t a;
    asm("{ .reg .u64 t; cvta.to.shared.u64 t, %1; cvt.u32.u64 %0, t; }" : "=r"(a) : "l"(p));
    return a;
}

__device__ __forceinline__ void cpa16(uint32_t dst, const void* src) {
    asm volatile("cp.async.cg.shared.global [%0], [%1], 16;" :: "r"(dst), "l"(src) : "memory");
}
#define CP_COMMIT()  asm volatile("cp.async.commit_group;" ::: "memory")
#define CP_WAIT(n)   asm volatile("cp.async.wait_group %0;" :: "n"(n) : "memory")

__device__ __forceinline__ void ldsm4(uint32_t a[4], uint32_t addr) {
    asm volatile("ldmatrix.sync.aligned.m8n8.x4.shared.b16 {%0,%1,%2,%3}, [%4];"
        : "=r"(a[0]), "=r"(a[1]), "=r"(a[2]), "=r"(a[3]) : "r"(addr));
}

__device__ __forceinline__ void mma16(float c[4], const uint32_t a[4],
                                      uint32_t b0, uint32_t b1) {
    asm volatile(
        "mma.sync.aligned.m16n8k16.row.col.f32.f16.f16.f32 "
        "{%0,%1,%2,%3}, {%4,%5,%6,%7}, {%8,%9}, {%0,%1,%2,%3};"
        : "+f"(c[0]), "+f"(c[1]), "+f"(c[2]), "+f"(c[3])
        : "r"(a[0]), "r"(a[1]), "r"(a[2]), "r"(a[3]), "r"(b0), "r"(b1));
}

// ---------------- kernel 0: zero counters -----------------------------------
__global__ void k_zero() {
    if (threadIdx.x < NEXP) g_count[threadIdx.x] = 0;
}

// ---------------- kernel 1: router (one warp per token) + x -> fp16 ---------
__global__ void k_router(const float* __restrict__ x, const float* __restrict__ gw) {
    int gtid = blockIdx.x * blockDim.x + threadIdx.x;
    int wid  = gtid >> 5;
    int lane = gtid & 31;
    if (wid >= T_TOK) return;

    const float* xr = x + (size_t)wid * DIM;
    __half*      xo = g_xh + (size_t)wid * DIM;
    float acc[8] = {0.f, 0.f, 0.f, 0.f, 0.f, 0.f, 0.f, 0.f};
    for (int d = lane; d < DIM; d += 32) {
        float xv = __ldg(xr + d);
        xo[d] = __float2half_rn(xv);
        const float4 g0 = *(const float4*)(gw + d * 8);
        const float4 g1 = *(const float4*)(gw + d * 8 + 4);
        acc[0] += xv * g0.x; acc[1] += xv * g0.y; acc[2] += xv * g0.z; acc[3] += xv * g0.w;
        acc[4] += xv * g1.x; acc[5] += xv * g1.y; acc[6] += xv * g1.z; acc[7] += xv * g1.w;
    }
#pragma unroll
    for (int i = 0; i < 8; i++) {
#pragma unroll
        for (int o = 16; o; o >>= 1) acc[i] += __shfl_xor_sync(0xffffffffu, acc[i], o);
    }
    if (lane == 0) {
        int e0 = 0;
#pragma unroll
        for (int i = 1; i < 8; i++) if (acc[i] > acc[e0]) e0 = i;
        int e1 = -1;
#pragma unroll
        for (int i = 0; i < 8; i++) {
            if (i == e0) continue;
            if (e1 < 0 || acc[i] > acc[e1]) e1 = i;
        }
        float m  = acc[e0];
        float p0 = expf(acc[e0] - m);
        float p1 = expf(acc[e1] - m);
        float s  = p0 + p1;

        int pos0 = atomicAdd(&g_count[e0], 1);
        g_tok [e0 * T_TOK + pos0] = wid;
        g_slot[e0 * T_TOK + pos0] = 0;
        g_coef[e0 * T_TOK + pos0] = p0 / s;
        int pos1 = atomicAdd(&g_count[e1], 1);
        g_tok [e1 * T_TOK + pos1] = wid;
        g_slot[e1 * T_TOK + pos1] = 1;
        g_coef[e1 * T_TOK + pos1] = p1 / s;
    }
}

// ---------------- kernel 1c: pack weights into B-fragment uint2 pairs -------
// src [e][K][N] fp32 -> dst [e][K/4][N] uint2; grid (N/1024, K/4, E), 4 n/thread
__global__ void k_pack2(const float* __restrict__ src, uint2* __restrict__ dst,
                        int K, int N) {
    int e  = blockIdx.z;
    int kq = blockIdx.y;
    int b  = kq >> 2, tig = kq & 3;
    int n  = (blockIdx.x * 256 + threadIdx.x) * 4;
    int k0 = 16 * b + 2 * tig;
    const float* s = src + (size_t)e * K * N + n;
    const float4 f0 = *(const float4*)(s + (size_t)(k0    ) * N);
    const float4 f1 = *(const float4*)(s + (size_t)(k0 + 1) * N);
    const float4 f2 = *(const float4*)(s + (size_t)(k0 + 8) * N);
    const float4 f3 = *(const float4*)(s + (size_t)(k0 + 9) * N);
    __half2 l0 = __floats2half2_rn(f0.x, f1.x), h0 = __floats2half2_rn(f2.x, f3.x);
    __half2 l1 = __floats2half2_rn(f0.y, f1.y), h1 = __floats2half2_rn(f2.y, f3.y);
    __half2 l2 = __floats2half2_rn(f0.z, f1.z), h2 = __floats2half2_rn(f2.z, f3.z);
    __half2 l3 = __floats2half2_rn(f0.w, f1.w), h3 = __floats2half2_rn(f2.w, f3.w);
    uint4 o0 = { *(uint32_t*)&l0, *(uint32_t*)&h0, *(uint32_t*)&l1, *(uint32_t*)&h1 };
    uint4 o1 = { *(uint32_t*)&l2, *(uint32_t*)&h2, *(uint32_t*)&l3, *(uint32_t*)&h3 };
    uint4* d = (uint4*)(dst + ((size_t)e * (K / 4) + kq) * N + n);
    d[0] = o0;
    d[1] = o1;
}

// ---------------- kernel 2: GEMM1 (x·w1, x·w3) + SwiGLU ---------------------
// grid (MLPD/BN, T_TOK/BM, NEXP), 512 threads = 16 warps (4M x 4N), warp tile 32x32
// BK=64, 3-stage cp.async, issue after barrier (WAR-safe).
__global__ __launch_bounds__(NTHREADS, 1)
void k_gemm1() {
    int e   = blockIdx.z;
    int cnt = g_count[e];
    int mt  = blockIdx.y;
    if (mt * BM >= cnt) return;
    int nt  = blockIdx.x;

    extern __shared__ uint32_t sm[];
    const int B1OFF = NST1 * A_STG;
    const int B3OFF = NST1 * A_STG + NST1 * B_STG;
    int* sTok = (int*)(sm + NST1 * A_STG + 2 * NST1 * B_STG);

    int tid    = threadIdx.x;
    int warpId = tid >> 5;
    int lane   = tid & 31;
    int gid    = lane >> 2;
    int tig    = lane & 3;
    int mBase  = (warpId & 3) * 32;
    int nBase  = (warpId >> 2) * 32;

    if (tid < BM) {
        int r = mt * BM + tid;
        sTok[tid] = (r < cnt) ? g_tok[e * T_TOK + r] : g_tok[e * T_TOK];
    }
    __syncthreads();

    uint32_t smB = smem_u32(sm);
    // A loader: 128 rows x 32 words = 1024 16B-chunks, 2 per thread
    int ar0 = tid >> 3, ag = tid & 7;            // rows 0-63, grp 0-7
    int ar1 = ar0 + 64;                          // rows 64-127
    const __half* srcA0 = g_xh + (size_t)sTok[ar0] * DIM + ag * 8;
    const __half* srcA1 = g_xh + (size_t)sTok[ar1] * DIM + ag * 8;
    uint32_t dA0 = smB + (ar0 * AP + ag * 4) * 4;
    uint32_t dA1 = smB + (ar1 * AP + ag * 4) * 4;
    // B loader: 16 kq-rows x 256 words = 1024 chunks, 2 per thread
    int br0 = tid >> 6, bg = tid & 63;           // rows 0-7
    int br1 = br0 + 8;                           // rows 8-15
    const uint2* srcB1a = g_w1p + ((size_t)e * (DIM / 4) + br0) * MLPD + nt * BN + bg * 2;
    const uint2* srcB1b = g_w1p + ((size_t)e * (DIM / 4) + br1) * MLPD + nt * BN + bg * 2;
    const uint2* srcB3a = g_w3p + ((size_t)e * (DIM / 4) + br0) * MLPD + nt * BN + bg * 2;
    const uint2* srcB3b = g_w3p + ((size_t)e * (DIM / 4) + br1) * MLPD + nt * BN + bg * 2;
    uint32_t dB1a = smB + (B1OFF + br0 * BQ + bg * 4) * 4;
    uint32_t dB1b = smB + (B1OFF + br1 * BQ + bg * 4) * 4;
    uint32_t dB3a = smB + (B3OFF + br0 * BQ + bg * 4) * 4;
    uint32_t dB3b = smB + (B3OFF + br1 * BQ + bg * 4) * 4;

    auto issue = [&](int s, int buf) {
        int ao = s * BK;                              // halfs
        size_t bo = (size_t)s * 16 * MLPD;            // uint2
        cpa16(dA0  + buf * A_STG * 4, srcA0  + ao);
        cpa16(dA1  + buf * A_STG * 4, srcA1  + ao);
        cpa16(dB1a + buf * B_STG * 4, srcB1a + bo);
        cpa16(dB1b + buf * B_STG * 4, srcB1b + bo);
        cpa16(dB3a + buf * B_STG * 4, srcB3a + bo);
        cpa16(dB3b + buf * B_STG * 4, srcB3b + bo);
        CP_COMMIT();
    };

    uint32_t aA = smB + ((mBase + (lane & 15)) * AP + (lane >> 4) * 4) * 4;
    int bIdx = tig * (BQ / 2) + nBase + gid;

    float c1[2][4][4], c3[2][4][4];
#pragma unroll
    for (int a = 0; a < 2; a++)
#pragma unroll
        for (int b = 0; b < 4; b++)
#pragma unroll
            for (int d = 0; d < 4; d++) { c1[a][b][d] = 0.f; c3[a][b][d] = 0.f; }

    const int NS = DIM / BK;   // 16
    issue(0, 0);
    issue(1, 1);

    int buf = 0;
    for (int s = 0; s < NS; s++) {
        if (s == NS - 1) { CP_WAIT(0); } else { CP_WAIT(1); }
        __syncthreads();
        if (s + 2 < NS) {
            int nb = buf + 2; if (nb >= NST1) nb -= NST1;
            issue(s + 2, nb);
        }

        const uint2* B1f = (const uint2*)(sm + B1OFF + buf * B_STG);
        const uint2* B3f = (const uint2*)(sm + B3OFF + buf * B_STG);
        uint32_t aBase = aA + buf * A_STG * 4;
#pragma unroll
        for (int kk = 0; kk < 4; kk++) {              // 4 k16 blocks per stage
            uint32_t a0[4], a1[4];
            ldsm4(a0, aBase + kk * 32);
            ldsm4(a1, aBase + 16 * AP * 4 + kk * 32);
            int kb = bIdx + kk * 4 * (BQ / 2);
#pragma unroll
            for (int ns = 0; ns < 4; ns++) {
                uint2 b1 = B1f[kb + ns * 8];
                uint2 b3 = B3f[kb + ns * 8];
                mma16(c1[0][ns], a0, b1.x, b1.y);
                mma16(c1[1][ns], a1, b1.x, b1.y);
                mma16(c3[0][ns], a0, b3.x, b3.y);
                mma16(c3[1][ns], a1, b3.x, b3.y);
            }
        }
        if (++buf >= NST1) buf = 0;
    }

    // SwiGLU epilogue -> g_h (fp16)
#pragma unroll
    for (int ms = 0; ms < 2; ms++) {
#pragma unroll
        for (int half = 0; half < 2; half++) {
            int grow = mt * BM + mBase + ms * 16 + gid + half * 8;
            if (grow < cnt) {
                size_t rowoff = ((size_t)e * T_TOK + grow) * MLPD;
#pragma unroll
                for (int ns = 0; ns < 4; ns++) {
                    int col = nt * BN + nBase + ns * 8 + tig * 2;
                    float v1a = c1[ms][ns][half * 2 + 0];
                    float v1b = c1[ms][ns][half * 2 + 1];
                    float v3a = c3[ms][ns][half * 2 + 0];
                    float v3b = c3[ms][ns][half * 2 + 1];
                    float ox = v1a / (1.f + __expf(-v1a)) * v3a;
                    float oy = v1b / (1.f + __expf(-v1b)) * v3b;
                    *(__half2*)(g_h + rowoff + col) = __floats2half2_rn(ox, oy);
                }
            }
        }
    }
}

// ---------------- kernel 3: GEMM2 (h·w2, scaled scatter to slot buffers) ----
// grid (DIM/BN, T_TOK/BM, NEXP), 512 threads, 2 CTAs/SM, BK=64, 2-stage
__global__ __launch_bounds__(NTHREADS, 2)
void k_gemm2() {
    int e   = blockIdx.z;
    int cnt = g_count[e];
    int mt  = blockIdx.y;
    if (mt * BM >= cnt) return;
    int nt  = blockIdx.x;

    extern __shared__ uint32_t sm[];
    const int BOFF = NST2 * A_STG;

    int tid    = threadIdx.x;
    int warpId = tid >> 5;
    int lane   = tid & 31;
    int gid    = lane >> 2;
    int tig    = lane & 3;
    int mBase  = (warpId & 3) * 32;
    int nBase  = (warpId >> 2) * 32;

    uint32_t smB = smem_u32(sm);
    int ar0 = tid >> 3, ag = tid & 7;
    int ar1 = ar0 + 64;
    // rows >= cnt read stale-but-finite h scratch; results discarded.
    const __half* srcA0 = g_h + ((size_t)e * T_TOK + (size_t)mt * BM + ar0) * MLPD + ag * 8;
    const __half* srcA1 = g_h + ((size_t)e * T_TOK + (size_t)mt * BM + ar1) * MLPD + ag * 8;
    uint32_t dA0 = smB + (ar0 * AP + ag * 4) * 4;
    uint32_t dA1 = smB + (ar1 * AP + ag * 4) * 4;
    int br0 = tid >> 6, bg = tid & 63;
    int br1 = br0 + 8;
    const uint2* srcBa = g_w2p + ((size_t)e * (MLPD / 4) + br0) * DIM + nt * BN + bg * 2;
    const uint2* srcBb = g_w2p + ((size_t)e * (MLPD / 4) + br1) * DIM + nt * BN + bg * 2;
    uint32_t dBa = smB + (BOFF + br0 * BQ + bg * 4) * 4;
    uint32_t dBb = smB + (BOFF + br1 * BQ + bg * 4) * 4;

    auto issue = [&](int s, int buf) {
        int ao = s * BK;
        size_t bo = (size_t)s * 16 * DIM;
        cpa16(dA0 + buf * A_STG * 4, srcA0 + ao);
        cpa16(dA1 + buf * A_STG * 4, srcA1 + ao);
        cpa16(dBa + buf * B_STG * 4, srcBa + bo);
        cpa16(dBb + buf * B_STG * 4, srcBb + bo);
        CP_COMMIT();
    };

    uint32_t aA = smB + ((mBase + (lane & 15)) * AP + (lane >> 4) * 4) * 4;
    int bIdx = tig * (BQ / 2) + nBase + gid;

    float c[2][4][4];
#pragma unroll
    for (int a = 0; a < 2; a++)
#pragma unroll
        for (int b = 0; b < 4; b++)
#pragma unroll
            for (int d = 0; d < 4; d++) c[a][b][d] = 0.f;

    const int NS = MLPD / BK;  // 32
    issue(0, 0);

    for (int s = 0; s < NS; s++) {
        int buf = s & 1;
        CP_WAIT(0);                      // group s (issued at s-1 / prologue) done
        __syncthreads();                 // all warps finished reading buf (s+1)&1
        if (s + 1 < NS) issue(s + 1, (s + 1) & 1);

        const uint2* Bf = (const uint2*)(sm + BOFF + buf * B_STG);
        uint32_t aBase = aA + buf * A_STG * 4;
#pragma unroll
        for (int kk = 0; kk < 4; kk++) {
            uint32_t a0[4], a1[4];
            ldsm4(a0, aBase + kk * 32);
            ldsm4(a1, aBase + 16 * AP * 4 + kk * 32);
            int kb = bIdx + kk * 4 * (BQ / 2);
#pragma unroll
            for (int ns = 0; ns < 4; ns++) {
                uint2 b = Bf[kb + ns * 8];
                mma16(c[0][ns], a0, b.x, b.y);
                mma16(c[1][ns], a1, b.x, b.y);
            }
        }
    }

    // scaled scatter into per-slot buffers (each (slot, token) cell written once)
#pragma unroll
    for (int ms = 0; ms < 2; ms++) {
#pragma unroll
        for (int half = 0; half < 2; half++) {
            int grow = mt * BM + mBase + ms * 16 + gid + half * 8;
            if (grow < cnt) {
                int   gi = e * T_TOK + grow;
                int   t  = g_tok[gi];
                int   sl = g_slot[gi];
                float cf = g_coef[gi];
                float* op = g_out2 + ((size_t)sl * T_TOK + t) * DIM + nt * BN + nBase;
#pragma unroll
                for (int ns = 0; ns < 4; ns++) {
                    int col = ns * 8 + tig * 2;
                    float2 o;
                    o.x = cf * c[ms][ns][half * 2 + 0];
                    o.y = cf * c[ms][ns][half * 2 + 1];
                    *(float2*)(op + col) = o;
                }
            }
        }
    }
}

// ---------------- kernel 4: combine slots -> output -------------------------
__global__ void k_combine(float* __restrict__ out) {
    size_t i = ((size_t)blockIdx.x * 256 + threadIdx.x) * 4;
    float4 a = *(const float4*)(g_out2 + i);
    float4 b = *(const float4*)(g_out2 + (size_t)T_TOK * DIM + i);
    float4 r;
    r.x = a.x + b.x; r.y = a.y + b.y; r.z = a.z + b.z; r.w = a.w + b.w;
    *(float4*)(out + i) = r;
}

// ---------------- launch -----------------------------------------------------
extern "C" void kernel_launch(void* const* d_in, const int* in_sizes, int n_in,
                              void* d_out, int out_size) {
    const float* x  = (const float*)d_in[0];
    const float* gw = (const float*)d_in[1];
    const float* w1 = (const float*)d_in[2];
    const float* w2 = (const float*)d_in[3];
    const float* w3 = (const float*)d_in[4];

    cudaFuncSetAttribute(k_gemm1, cudaFuncAttributeMaxDynamicSharedMemorySize, SMEM1_BYTES);
    cudaFuncSetAttribute(k_gemm2, cudaFuncAttributeMaxDynamicSharedMemorySize, SMEM2_BYTES);

    k_zero<<<1, 32>>>();
    k_router<<<T_TOK / 8, 256>>>(x, gw);

    uint2* w1p; cudaGetSymbolAddress((void**)&w1p, g_w1p);
    uint2* w3p; cudaGetSymbolAddress((void**)&w3p, g_w3p);
    uint2* w2p; cudaGetSymbolAddress((void**)&w2p, g_w2p);
    k_pack2<<<dim3(MLPD / 1024, DIM / 4, NEXP), 256>>>(w1, w1p, DIM, MLPD);
    k_pack2<<<dim3(MLPD / 1024, DIM / 4, NEXP), 256>>>(w3, w3p, DIM, MLPD);
    k_pack2<<<dim3(DIM / 1024, MLPD / 4, NEXP), 256>>>(w2, w2p, MLPD, DIM);

    k_gemm1<<<dim3(MLPD / BN, T_TOK / BM, NEXP), NTHREADS, SMEM1_BYTES>>>();
    k_gemm2<<<dim3(DIM / BN, T_TOK / BM, NEXP), NTHREADS, SMEM2_BYTES>>>();

    k_combine<<<(T_TOK * DIM / 4) / 256, 256>>>((float*)d_out);
}